// round 15
// baseline (speedup 1.0000x reference)
#include <cuda_runtime.h>
#include <cuda_bf16.h>
#include <cuda_fp16.h>
#include <cstdint>

// Problem constants
#define M_ROWS 1024      // B*S
#define HDIM   1024
#define HD2    512
#define VDIM   32000
#define N_EXP  128000    // K*V
#define NBLK   1000      // n-blocks of 128 in expert GEMM (250 per expert)

// ---------------- scratch (device globals; no runtime allocation) ----------------
__device__ __align__(16) __nv_bfloat16 g_xbf[M_ROWS * HDIM];            // RMSNormed x (2 MB)
__device__ __align__(16) __nv_bfloat16 g_wt[(size_t)N_EXP * HDIM];      // expert_w^T bf16 (262 MB)
__device__ __align__(16) float         g_gsilu[M_ROWS * HD2];
__device__ __align__(16) float         g_gw[M_ROWS * 4];
__device__ __align__(16) __half        g_E[(size_t)M_ROWS * N_EXP];     // exp(logits) (262 MB)
__device__ __align__(16) float         g_psum[(size_t)M_ROWS * NBLK];   // per-block row sums (4 MB)

// ---------------- helpers ----------------
__device__ __forceinline__ uint32_t cvta_s(const void* p) {
    return (uint32_t)__cvta_generic_to_shared(p);
}
// SW128 swizzle on byte offsets (1KB atom, 128B rows)
__device__ __forceinline__ uint32_t swz128(uint32_t o) { return o ^ ((o >> 3) & 0x70); }

__device__ __forceinline__ void ldsm_x4(uint32_t& r0, uint32_t& r1, uint32_t& r2, uint32_t& r3,
                                        uint32_t addr) {
    asm volatile("ldmatrix.sync.aligned.m8n8.x4.shared.b16 {%0,%1,%2,%3}, [%4];"
                 : "=r"(r0), "=r"(r1), "=r"(r2), "=r"(r3) : "r"(addr));
}

// ---------------- K0: transpose + convert expert_w fp32[K][N] -> bf16[N][K] ----------------
// (R14 version — LDG.128 reads, proven at DRAM floor; g_wt bit-identical to R8)
__global__ __launch_bounds__(256) void transpose_convert(const float* __restrict__ W)
{
    __shared__ float t[64][33];
    const int n0 = (int)(gridDim.x - 1 - blockIdx.x) * 32;   // reversed n order
    const int k0 = blockIdx.y * 64;
    const int tid = threadIdx.x;

    {
        const int f4 = tid & 7;
        const int kr = tid >> 3;
        float4 v0 = *reinterpret_cast<const float4*>(W + (size_t)(k0 + kr)      * N_EXP + n0 + f4 * 4);
        float4 v1 = *reinterpret_cast<const float4*>(W + (size_t)(k0 + kr + 32) * N_EXP + n0 + f4 * 4);
        t[kr][f4*4+0] = v0.x; t[kr][f4*4+1] = v0.y; t[kr][f4*4+2] = v0.z; t[kr][f4*4+3] = v0.w;
        t[kr+32][f4*4+0] = v1.x; t[kr+32][f4*4+1] = v1.y; t[kr+32][f4*4+2] = v1.z; t[kr+32][f4*4+3] = v1.w;
    }
    __syncthreads();
    const int kk = (tid & 31) * 2;
    #pragma unroll
    for (int i = 0; i < 4; i++) {
        int nl = (tid >> 5) + i * 8;
        __nv_bfloat162 p = __floats2bfloat162_rn(t[kk][nl], t[kk + 1][nl]);
        *reinterpret_cast<__nv_bfloat162*>(&g_wt[(size_t)(n0 + nl) * HDIM + k0 + kk]) = p;
    }
}

// ---------------- K1: RMSNorm -> bf16 ----------------
__global__ __launch_bounds__(256) void rmsnorm_kernel(const float* __restrict__ hs,
                                                      const float* __restrict__ scale)
{
    const int r = blockIdx.x, tid = threadIdx.x;
    __shared__ float red[256];
    const float4* xp = (const float4*)(hs + (size_t)r * HDIM);
    float4 v = xp[tid];
    red[tid] = v.x*v.x + v.y*v.y + v.z*v.z + v.w*v.w;
    __syncthreads();
    #pragma unroll
    for (int s = 128; s > 0; s >>= 1) {
        if (tid < s) red[tid] += red[tid + s];
        __syncthreads();
    }
    float inv = rsqrtf(red[0] * (1.0f / HDIM) + 1e-5f);
    float4 sc = ((const float4*)scale)[tid];
    __nv_bfloat162 p0 = __floats2bfloat162_rn(v.x*inv*sc.x, v.y*inv*sc.y);
    __nv_bfloat162 p1 = __floats2bfloat162_rn(v.z*inv*sc.z, v.w*inv*sc.w);
    uint2 u;
    u.x = *reinterpret_cast<unsigned*>(&p0);
    u.y = *reinterpret_cast<unsigned*>(&p1);
    *reinterpret_cast<uint2*>(&g_xbf[(size_t)r * HDIM + tid * 4]) = u;
}

// ---------------- K2: gate-down GEMM (small) ----------------
__global__ __launch_bounds__(256) void gemm_gate(const float* __restrict__ Bmat,
                                                 const float* __restrict__ bias)
{
    __shared__ __align__(16) __nv_bfloat16 As[128][40];
    __shared__ __align__(16) __nv_bfloat16 Bs[128][40];

    const int tid  = threadIdx.x;
    const int lane = tid & 31;
    const int warp = tid >> 5;
    const int wm = warp >> 2, wn = warp & 3;
    const int m0 = blockIdx.x * 128;
    const int n0 = blockIdx.y * 128;
    const int ldb = HD2;

    float acc[4][4][4];
    #pragma unroll
    for (int i = 0; i < 4; i++)
        #pragma unroll
        for (int j = 0; j < 4; j++)
            #pragma unroll
            for (int q = 0; q < 4; q++) acc[i][j][q] = 0.0f;

    const int l_row = tid & 127, k_half = tid >> 7;

    for (int k0 = 0; k0 < HDIM; k0 += 32) {
        {
            const __nv_bfloat16* Ap = g_xbf + (size_t)(m0 + l_row) * HDIM + k0 + k_half * 16;
            *reinterpret_cast<uint4*>(&As[l_row][k_half * 16])     = *(const uint4*)Ap;
            *reinterpret_cast<uint4*>(&As[l_row][k_half * 16 + 8]) = *(const uint4*)(Ap + 8);
        }
        {
            const float* Bp = Bmat + (size_t)(k0 + k_half * 16) * ldb + n0 + l_row;
            unsigned rr[8];
            #pragma unroll
            for (int j = 0; j < 8; j++) {
                __nv_bfloat162 p = __floats2bfloat162_rn(Bp[(size_t)(2*j)*ldb], Bp[(size_t)(2*j+1)*ldb]);
                rr[j] = *reinterpret_cast<unsigned*>(&p);
            }
            *reinterpret_cast<uint4*>(&Bs[l_row][k_half * 16])     = make_uint4(rr[0],rr[1],rr[2],rr[3]);
            *reinterpret_cast<uint4*>(&Bs[l_row][k_half * 16 + 8]) = make_uint4(rr[4],rr[5],rr[6],rr[7]);
        }
        __syncthreads();
        #pragma unroll
        for (int ks = 0; ks < 2; ks++) {
            const int kc = ks * 16 + (lane & 3) * 2;
            unsigned a[4][4], b[4][2];
            #pragma unroll
            for (int mt = 0; mt < 4; mt++) {
                int r0 = wm * 64 + mt * 16 + (lane >> 2);
                a[mt][0] = *reinterpret_cast<const unsigned*>(&As[r0    ][kc    ]);
                a[mt][1] = *reinterpret_cast<const unsigned*>(&As[r0 + 8][kc    ]);
                a[mt][2] = *reinterpret_cast<const unsigned*>(&As[r0    ][kc + 8]);
                a[mt][3] = *reinterpret_cast<const unsigned*>(&As[r0 + 8][kc + 8]);
            }
            #pragma unroll
            for (int nt = 0; nt < 4; nt++) {
                int c0 = wn * 32 + nt * 8 + (lane >> 2);
                b[nt][0] = *reinterpret_cast<const unsigned*>(&Bs[c0][kc    ]);
                b[nt][1] = *reinterpret_cast<const unsigned*>(&Bs[c0][kc + 8]);
            }
            #pragma unroll
            for (int mt = 0; mt < 4; mt++)
                #pragma unroll
                for (int nt = 0; nt < 4; nt++) {
                    asm volatile(
                        "mma.sync.aligned.m16n8k16.row.col.f32.bf16.bf16.f32 "
                        "{%0,%1,%2,%3}, {%4,%5,%6,%7}, {%8,%9}, {%0,%1,%2,%3};\n"
                        : "+f"(acc[mt][nt][0]), "+f"(acc[mt][nt][1]),
                          "+f"(acc[mt][nt][2]), "+f"(acc[mt][nt][3])
                        : "r"(a[mt][0]), "r"(a[mt][1]), "r"(a[mt][2]), "r"(a[mt][3]),
                          "r"(b[nt][0]), "r"(b[nt][1]));
                }
        }
        __syncthreads();
    }
    #pragma unroll
    for (int mt = 0; mt < 4; mt++) {
        int r0 = m0 + wm * 64 + mt * 16 + (lane >> 2);
        #pragma unroll
        for (int nt = 0; nt < 4; nt++) {
            int nc = n0 + wn * 32 + nt * 8 + (lane & 3) * 2;
            float b0 = bias[nc], b1 = bias[nc + 1];
            float v;
            v = acc[mt][nt][0] + b0; g_gsilu[r0 * HD2 + nc]           = v / (1.0f + __expf(-v));
            v = acc[mt][nt][1] + b1; g_gsilu[r0 * HD2 + nc + 1]       = v / (1.0f + __expf(-v));
            v = acc[mt][nt][2] + b0; g_gsilu[(r0 + 8) * HD2 + nc]     = v / (1.0f + __expf(-v));
            v = acc[mt][nt][3] + b1; g_gsilu[(r0 + 8) * HD2 + nc + 1] = v / (1.0f + __expf(-v));
        }
    }
}

// ---------------- K3: gate-up GEMV + softmax over 4 experts ----------------
__global__ __launch_bounds__(128) void gate_softmax_kernel(const float* __restrict__ Wu,
                                                           const float* __restrict__ bu)
{
    const int r = blockIdx.x, tid = threadIdx.x;
    float p0 = 0.f, p1 = 0.f, p2 = 0.f, p3 = 0.f;
    const float* gr = g_gsilu + (size_t)r * HD2;
    for (int d = tid; d < HD2; d += 128) {
        float gv = gr[d];
        float4 w = ((const float4*)Wu)[d];
        p0 += gv * w.x; p1 += gv * w.y; p2 += gv * w.z; p3 += gv * w.w;
    }
    __shared__ float red[4][128];
    red[0][tid] = p0; red[1][tid] = p1; red[2][tid] = p2; red[3][tid] = p3;
    __syncthreads();
    #pragma unroll
    for (int s = 64; s > 0; s >>= 1) {
        if (tid < s) {
            red[0][tid] += red[0][tid + s]; red[1][tid] += red[1][tid + s];
            red[2][tid] += red[2][tid + s]; red[3][tid] += red[3][tid + s];
        }
        __syncthreads();
    }
    if (tid == 0) {
        float l[4];
        #pragma unroll
        for (int k = 0; k < 4; k++) l[k] = red[k][0] + bu[k];
        float m = fmaxf(fmaxf(l[0], l[1]), fmaxf(l[2], l[3]));
        float e[4]; float s = 0.f;
        #pragma unroll
        for (int k = 0; k < 4; k++) { e[k] = __expf(l[k] - m); s += e[k]; }
        float inv = 1.0f / s;
        #pragma unroll
        for (int k = 0; k < 4; k++) g_gw[r * 4 + k] = e[k] * inv;
    }
}

// ---------------- K4: expert GEMM (FROZEN R12 config: 3-stage, 2 CTAs/SM) ----------------
// CTA tile 128x128, BK=64, 16 k-tiles, 4 warps (2m x 2n), warp tile 64x64.
#define STAGE_BYTES 32768
#define B_OFF       16384
#define SMEM_GEMM   99328

extern __shared__ char dsm[];

__global__ void __launch_bounds__(128, 2) expert_gemm()
{
    const int tid  = threadIdx.x;
    const int lane = tid & 31;
    const int warp = tid >> 5;
    const int wm = warp >> 1, wn = warp & 1;   // 2x2 warp grid, warp tile 64x64
    const int m0 = blockIdx.x * 128;
    const int n0 = blockIdx.y * 128;
    const uint32_t sbase = cvta_s(dsm);

    float acc[4][8][4];
    #pragma unroll
    for (int i = 0; i < 4; i++)
        #pragma unroll
        for (int j = 0; j < 8; j++)
            #pragma unroll
            for (int q = 0; q < 4; q++) acc[i][j][q] = 0.0f;

    // ---- cp.async stage loader: 128 threads, 16B each, 8 rows A + 8 rows B ----
    const int lrow = tid >> 3;            // 0..15
    const int seg  = tid & 7;             // 0..7
    const __nv_bfloat16* Abase_g = g_xbf + (size_t)(m0 + lrow) * HDIM + seg * 8;
    const __nv_bfloat16* Bbase_g = g_wt  + (size_t)(n0 + lrow) * HDIM + seg * 8;

    auto load_stage = [&](int kt, int buf) {
        const uint32_t sA = sbase + buf * STAGE_BYTES;
        const uint32_t sB = sA + B_OFF;
        const int koff = kt * 64;
        #pragma unroll
        for (int i = 0; i < 8; i++) {
            uint32_t d = sA + swz128((lrow + i * 16) * 128 + seg * 16);
            asm volatile("cp.async.cg.shared.global [%0], [%1], 16;"
                         :: "r"(d), "l"(Abase_g + koff + (size_t)i * 16 * HDIM) : "memory");
        }
        #pragma unroll
        for (int i = 0; i < 8; i++) {
            uint32_t d = sB + swz128((lrow + i * 16) * 128 + seg * 16);
            asm volatile("cp.async.cg.shared.global [%0], [%1], 16;"
                         :: "r"(d), "l"(Bbase_g + koff + (size_t)i * 16 * HDIM) : "memory");
        }
        asm volatile("cp.async.commit_group;" ::: "memory");
    };

    load_stage(0, 0);
    load_stage(1, 1);

    // per-lane ldmatrix address components (verified R6 maps)
    const int a_row_in16 = lane & 15;          // row within m16 tile
    const int a_khalf    = (lane >> 4) * 16;   // 0 or 16 bytes
    const int b_nrow     = (lane & 7) + ((lane >> 4) & 1) * 8;  // row within n16 pair
    const int b_khalf    = ((lane >> 3) & 1) * 16;

    for (int kt = 0; kt < 16; kt++) {
        const int buf = kt % 3;
        if (kt < 15) asm volatile("cp.async.wait_group 1;" ::: "memory");
        else         asm volatile("cp.async.wait_group 0;" ::: "memory");
        __syncthreads();   // stage kt visible; all warps done with kt-1's buffer
        if (kt + 2 < 16) load_stage(kt + 2, (kt + 2) % 3);

        const uint32_t sA = sbase + buf * STAGE_BYTES;
        const uint32_t sB = sA + B_OFF;

        #pragma unroll
        for (int ks = 0; ks < 4; ks++) {
            const int kb = ks * 32;            // byte offset of this k16 step
            unsigned a[4][4], b[8][2];
            #pragma unroll
            for (int mt = 0; mt < 4; mt++) {
                int row = wm * 64 + mt * 16 + a_row_in16;
                uint32_t addr = sA + row * 128 + ((kb + a_khalf) ^ ((row & 7) * 16));
                ldsm_x4(a[mt][0], a[mt][1], a[mt][2], a[mt][3], addr);
            }
            #pragma unroll
            for (int np = 0; np < 4; np++) {   // pairs of n8 tiles
                int row = wn * 64 + np * 16 + b_nrow;
                uint32_t addr = sB + row * 128 + ((kb + b_khalf) ^ ((row & 7) * 16));
                ldsm_x4(b[np*2][0], b[np*2][1], b[np*2+1][0], b[np*2+1][1], addr);
            }
            #pragma unroll
            for (int mt = 0; mt < 4; mt++)
                #pragma unroll
                for (int nt = 0; nt < 8; nt++) {
                    asm volatile(
                        "mma.sync.aligned.m16n8k16.row.col.f32.bf16.bf16.f32 "
                        "{%0,%1,%2,%3}, {%4,%5,%6,%7}, {%8,%9}, {%0,%1,%2,%3};\n"
                        : "+f"(acc[mt][nt][0]), "+f"(acc[mt][nt][1]),
                          "+f"(acc[mt][nt][2]), "+f"(acc[mt][nt][3])
                        : "r"(a[mt][0]), "r"(a[mt][1]), "r"(a[mt][2]), "r"(a[mt][3]),
                          "r"(b[nt][0]), "r"(b[nt][1]));
                }
        }
    }

    // ---- epilogue: exp -> fp16 store + deterministic row sums ----
    __syncthreads();   // all compute done before s_rows staging
    float* s_rows = reinterpret_cast<float*>(dsm + 3 * STAGE_BYTES);   // [2][128]
    float rs[4][2];
    #pragma unroll
    for (int mt = 0; mt < 4; mt++) { rs[mt][0] = 0.f; rs[mt][1] = 0.f; }

    #pragma unroll
    for (int mt = 0; mt < 4; mt++) {
        int rg = m0 + wm * 64 + mt * 16 + (lane >> 2);
        #pragma unroll
        for (int nt = 0; nt < 8; nt++) {
            int nc = n0 + wn * 64 + nt * 8 + (lane & 3) * 2;
            float e0 = __expf(acc[mt][nt][0]);
            float e1 = __expf(acc[mt][nt][1]);
            float e2 = __expf(acc[mt][nt][2]);
            float e3 = __expf(acc[mt][nt][3]);
            rs[mt][0] += e0 + e1;
            rs[mt][1] += e2 + e3;
            __half2 h0 = __floats2half2_rn(e0, e1);
            __half2 h1 = __floats2half2_rn(e2, e3);
            *reinterpret_cast<__half2*>(&g_E[(size_t)rg * N_EXP + nc])       = h0;
            *reinterpret_cast<__half2*>(&g_E[(size_t)(rg + 8) * N_EXP + nc]) = h1;
        }
    }
    // quad-reduce (lanes sharing the same rows) then stage per-warp-column partials
    #pragma unroll
    for (int mt = 0; mt < 4; mt++) {
        #pragma unroll
        for (int h = 0; h < 2; h++) {
            float v = rs[mt][h];
            v += __shfl_xor_sync(0xffffffff, v, 1);
            v += __shfl_xor_sync(0xffffffff, v, 2);
            if ((lane & 3) == 0)
                s_rows[wn * 128 + wm * 64 + mt * 16 + (lane >> 2) + h * 8] = v;
        }
    }
    __syncthreads();
    if (tid < 128) {
        float t = s_rows[tid] + s_rows[128 + tid];
        g_psum[(size_t)(m0 + tid) * NBLK + blockIdx.y] = t;
    }
}

// ---------------- K5: coefs from psums + mixture + log (uint4 E loads, float4 stores) ----------------
__global__ __launch_bounds__(256) void mix_out_kernel(float* __restrict__ out)
{
    const int r = blockIdx.x, tid = threadIdx.x;
    __shared__ float s_coef[4];
    if (tid < 128) {
        int e = tid >> 5, lane = tid & 31;
        float a = 0.f;
        for (int j = lane; j < 250; j += 32)
            a += g_psum[(size_t)r * NBLK + e * 250 + j];
        #pragma unroll
        for (int s = 16; s; s >>= 1) a += __shfl_xor_sync(0xffffffff, a, s);
        if (lane == 0) s_coef[e] = g_gw[r * 4 + e] / a;
    }
    __syncthreads();
    const float c0 = s_coef[0], c1 = s_coef[1], c2 = s_coef[2], c3 = s_coef[3];

    const uint4* E4 = reinterpret_cast<const uint4*>(g_E + (size_t)r * N_EXP);
    float4* out4 = reinterpret_cast<float4*>(out + (size_t)r * VDIM);
    const int Q = VDIM / 8;                  // 4000 uint4 per expert stream

    for (int v = tid; v < Q; v += 256) {
        uint4 q0 = E4[v];
        uint4 q1 = E4[Q + v];
        uint4 q2 = E4[2 * Q + v];
        uint4 q3 = E4[3 * Q + v];
        float o[8];
        #pragma unroll
        for (int w = 0; w < 4; w++) {
            float2 f0 = __half22float2(*reinterpret_cast<const __half2*>(&(&q0.x)[w]));
            float2 f1 = __half22float2(*reinterpret_cast<const __half2*>(&(&q1.x)[w]));
            float2 f2 = __half22float2(*reinterpret_cast<const __half2*>(&(&q2.x)[w]));
            float2 f3 = __half22float2(*reinterpret_cast<const __half2*>(&(&q3.x)[w]));
            o[2*w]   = __logf(c0 * f0.x + c1 * f1.x + c2 * f2.x + c3 * f3.x + 1e-10f);
            o[2*w+1] = __logf(c0 * f0.y + c1 * f1.y + c2 * f2.y + c3 * f3.y + 1e-10f);
        }
        out4[2 * v]     = make_float4(o[0], o[1], o[2], o[3]);
        out4[2 * v + 1] = make_float4(o[4], o[5], o[6], o[7]);
    }
}

// ---------------- launch ----------------
// Fork-join overlap: transpose_convert (DRAM-bound, independent) runs on a
// second stream concurrently with the rmsnorm -> gate chain; both join before
// expert_gemm. Event edges make this capturable as a proper graph DAG.
extern "C" void kernel_launch(void* const* d_in, const int* in_sizes, int n_in,
                              void* d_out, int out_size)
{
    const float* hs  = (const float*)d_in[0];
    const float* rs  = (const float*)d_in[1];
    const float* gdw = (const float*)d_in[2];
    const float* gdb = (const float*)d_in[3];
    const float* guw = (const float*)d_in[4];
    const float* gub = (const float*)d_in[5];
    const float* ew  = (const float*)d_in[6];
    float* out = (float*)d_out;

    static cudaStream_t s2 = nullptr;
    static cudaEvent_t ev_fork = nullptr, ev_join = nullptr;
    if (s2 == nullptr) {
        cudaStreamCreateWithFlags(&s2, cudaStreamNonBlocking);
        cudaEventCreateWithFlags(&ev_fork, cudaEventDisableTiming);
        cudaEventCreateWithFlags(&ev_join, cudaEventDisableTiming);
        cudaFuncSetAttribute(expert_gemm, cudaFuncAttributeMaxDynamicSharedMemorySize, SMEM_GEMM);
    }

    // fork: s2 inherits everything enqueued so far on the default stream
    cudaEventRecord(ev_fork, 0);
    cudaStreamWaitEvent(s2, ev_fork, 0);

    // branch A (stream s2): big independent transpose/convert
    transpose_convert<<<dim3(N_EXP / 32, HDIM / 64), 256, 0, s2>>>(ew);

    // branch B (default stream): rmsnorm -> gate chain
    rmsnorm_kernel<<<M_ROWS, 256>>>(hs, rs);
    gemm_gate<<<dim3(8, 4), 256>>>(gdw, gdb);
    gate_softmax_kernel<<<M_ROWS, 128>>>(guw, gub);

    // join: expert_gemm needs both g_wt (s2) and g_xbf/g_gw (default)
    cudaEventRecord(ev_join, s2);
    cudaStreamWaitEvent(0, ev_join, 0);

    expert_gemm<<<dim3(8, NBLK), 128, SMEM_GEMM>>>();
    mix_out_kernel<<<M_ROWS, 256>>>(out);
}